// round 15
// baseline (speedup 1.0000x reference)
#include <cuda_runtime.h>
#include <cuda_fp16.h>
#include <math.h>
#include <stdint.h>

// Problem dims
#define N_  128
#define M_  2048
#define DX_ 64
#define DY_ 8
#define DU_ 256
#define DZ_ 256

// ---------------- device scratch (static, no allocations) ----------------
__device__ __align__(16) __half g_sp1h[DZ_ * DZ_];  // fp16(softplus(Wz1)) [k][z]
__device__ __align__(16) float g_WT0  [DX_ * DU_];  // Wt0^T  [d][k]
__device__ __align__(16) float g_WuT0 [DX_ * DZ_];  // Wu0^T
__device__ __align__(16) float g_WT1  [DU_ * DU_];  // Wt1^T
__device__ __align__(16) float g_WzuT1[DU_ * DZ_];  // Wzu1^T
__device__ __align__(16) float g_WuT1 [DU_ * DZ_];  // Wu1^T
__device__ __align__(16) float g_WzuT2[DU_ * DZ_];  // Wzu2^T
__device__ __align__(16) float g_gy0[N_ * DY_];
__device__ __align__(16) float g_c0 [N_ * DZ_];
__device__ __align__(16) float g_gz1[N_ * DZ_];
__device__ __align__(16) float g_gy1[N_ * DY_];
__device__ __align__(16) float g_c1 [N_ * DZ_];
__device__ __align__(16) float g_gk2[N_ * DZ_];     // gz2 * softplus(Wz2)
__device__ __align__(16) float g_w2d[N_ * DY_];     // gy2 * Wy2
__device__ __align__(16) float g_c2 [N_];
__device__ __align__(16) float g_slack[N_ * M_];

__device__ __forceinline__ float softplus_f(float x) {
    return fmaxf(x, 0.f) + log1pf(expf(-fabsf(x)));
}

#define CP_ASYNC16(dst, src) \
    asm volatile("cp.async.cg.shared.global [%0], [%1], 16;" \
        :: "r"((uint32_t)(dst)), "l"(src) : "memory")
#define CP_COMMIT() asm volatile("cp.async.commit_group;" ::: "memory")
#define CP_WAIT0()  asm volatile("cp.async.wait_group 0;" ::: "memory")

__device__ __forceinline__ uint32_t smem_u32(const void* p) {
    uint32_t a;
    asm("{ .reg .u64 t; cvta.to.shared.u64 t, %1; cvt.u32.u64 %0, t; }"
        : "=r"(a) : "l"(p));
    return a;
}

// m16n8k16 fp16 MMA, fp32 accumulate
__device__ __forceinline__ void mma_f16(float* c, const uint32_t* a,
                                        uint32_t b0, uint32_t b1) {
    asm volatile(
        "mma.sync.aligned.m16n8k16.row.col.f32.f16.f16.f32 "
        "{%0,%1,%2,%3}, {%4,%5,%6,%7}, {%8,%9}, {%0,%1,%2,%3};"
        : "+f"(c[0]), "+f"(c[1]), "+f"(c[2]), "+f"(c[3])
        : "r"(a[0]), "r"(a[1]), "r"(a[2]), "r"(a[3]), "r"(b0), "r"(b1));
}

#define LDSM_X4(r0, r1, r2, r3, addr) \
    asm volatile("ldmatrix.sync.aligned.m8n8.x4.shared.b16 {%0,%1,%2,%3}, [%4];" \
        : "=r"(r0), "=r"(r1), "=r"(r2), "=r"(r3) : "r"(addr))

__device__ __forceinline__ uint32_t pack_h2(float lo, float hi) {
    __half2 h = __floats2half2_rn(lo, hi);
    return *(uint32_t*)&h;
}

// ---------------- kernel 0a: fp16(softplus(Wz1)) ----------------
__global__ void sp1_kernel(const float* __restrict__ Wz1) {
    int i = blockIdx.x * 256 + threadIdx.x;
    g_sp1h[i] = __float2half_rn(softplus_f(Wz1[i]));
}

// ---------------- kernel 0b: transpose the 256x256 setup weights ----------------
// grid (8, 8, 4), block (32, 8)
__global__ void tr256_kernel(const float* __restrict__ Wt1,
                             const float* __restrict__ Wzu1,
                             const float* __restrict__ Wu1,
                             const float* __restrict__ Wzu2)
{
    __shared__ float t[32][33];
    const float* A;
    float* B;
    switch (blockIdx.z) {
        case 0:  A = Wt1;  B = g_WT1;   break;
        case 1:  A = Wzu1; B = g_WzuT1; break;
        case 2:  A = Wu1;  B = g_WuT1;  break;
        default: A = Wzu2; B = g_WzuT2; break;
    }
    const int tx = threadIdx.x, ty = threadIdx.y;
    int xIn = blockIdx.x * 32 + tx;
    int yIn = blockIdx.y * 32 + ty;
    #pragma unroll
    for (int j = 0; j < 32; j += 8)
        t[ty + j][tx] = A[(yIn + j) * 256 + xIn];
    __syncthreads();
    int xOut = blockIdx.y * 32 + tx;
    int yOut = blockIdx.x * 32 + ty;
    #pragma unroll
    for (int j = 0; j < 32; j += 8)
        B[(yOut + j) * 256 + xOut] = t[tx][ty + j];
}

// ---------------- kernel 0c: transpose the 256x64 setup weights ----------------
// grid (2, 8, 2), block (32, 8)   A: 256 rows x 64 cols -> B: 64 x 256
__global__ void tr64_kernel(const float* __restrict__ Wt0,
                            const float* __restrict__ Wu0)
{
    __shared__ float t[32][33];
    const float* A = blockIdx.z ? Wu0 : Wt0;
    float* B       = blockIdx.z ? g_WuT0 : g_WT0;
    const int tx = threadIdx.x, ty = threadIdx.y;
    int xIn = blockIdx.x * 32 + tx;          // col in A (<64)
    int yIn = blockIdx.y * 32 + ty;          // row in A (<256)
    #pragma unroll
    for (int j = 0; j < 32; j += 8)
        t[ty + j][tx] = A[(yIn + j) * DX_ + xIn];
    __syncthreads();
    int xOut = blockIdx.y * 32 + tx;         // col in B (<256)
    int yOut = blockIdx.x * 32 + ty;         // row in B (<64)
    #pragma unroll
    for (int j = 0; j < 32; j += 8)
        B[(yOut + j) * 256 + xOut] = t[tx][ty + j];
}

// ---------------- kernel 1: per-n setup (coalesced, 2 n per CTA) ----------------
// grid 64, block 256
__global__ void setup_kernel(
    const float* __restrict__ X,
    const float* __restrict__ bt0,  const float* __restrict__ bt1,
    const float* __restrict__ Wyu0, const float* __restrict__ byu0,
    const float* __restrict__ b0,
    const float* __restrict__ bzu1,
    const float* __restrict__ Wyu1, const float* __restrict__ byu1,
    const float* __restrict__ b1,
    const float* __restrict__ bzu2, const float* __restrict__ Wz2,
    const float* __restrict__ Wyu2, const float* __restrict__ byu2,
    const float* __restrict__ Wy2,
    const float* __restrict__ Wu2,  const float* __restrict__ b2)
{
    __shared__ __align__(16) float xs[2][DX_];
    __shared__ __align__(16) float u1s[2][DU_];
    __shared__ __align__(16) float u2s[2][DU_];
    __shared__ float wred[2][8];
    const int n0 = blockIdx.x * 2;
    const int k = threadIdx.x;

    if (k < 32) ((float4*)xs)[k] = ((const float4*)(X + n0 * DX_))[k];
    __syncthreads();

    // ---- stage 1: u1, c0 (in-dim 64, transposed weights, coalesced) ----
    {
        float ua = 0.f, ub = 0.f, ca = 0.f, cb = 0.f;
        #pragma unroll 8
        for (int d = 0; d < DX_; ++d) {
            float wt = g_WT0[d * 256 + k];
            float wu = g_WuT0[d * 256 + k];
            float x0 = xs[0][d], x1 = xs[1][d];
            ua = fmaf(wt, x0, ua); ub = fmaf(wt, x1, ub);
            ca = fmaf(wu, x0, ca); cb = fmaf(wu, x1, cb);
        }
        float bb = bt0[k], bv = b0[k];
        u1s[0][k] = fmaxf(ua + bb, 0.f);
        u1s[1][k] = fmaxf(ub + bb, 0.f);
        g_c0[n0 * DZ_ + k]       = ca + bv;
        g_c0[(n0 + 1) * DZ_ + k] = cb + bv;
    }
    if (k < DY_) {
        #pragma unroll
        for (int nn = 0; nn < 2; ++nn) {
            float s0 = 0.f, s1 = 0.f;
            #pragma unroll 8
            for (int d = 0; d < DX_; d += 2) {
                s0 = fmaf(Wyu0[k * DX_ + d],     xs[nn][d],     s0);
                s1 = fmaf(Wyu0[k * DX_ + d + 1], xs[nn][d + 1], s1);
            }
            g_gy0[(n0 + nn) * DY_ + k] = s0 + s1 + byu0[k];
        }
    }
    __syncthreads();

    // ---- stage 2: u2, gz1, c1 (in-dim 256, 3 weights, 6 chains) ----
    float u2a, u2b;
    {
        float ta = 0.f, tb = 0.f, za = 0.f, zb = 0.f, ca = 0.f, cb = 0.f;
        #pragma unroll 4
        for (int d = 0; d < DU_; ++d) {
            float u0v = u1s[0][d], u1v = u1s[1][d];
            float w1 = g_WT1  [d * 256 + k];
            float w2 = g_WzuT1[d * 256 + k];
            float w3 = g_WuT1 [d * 256 + k];
            ta = fmaf(w1, u0v, ta); tb = fmaf(w1, u1v, tb);
            za = fmaf(w2, u0v, za); zb = fmaf(w2, u1v, zb);
            ca = fmaf(w3, u0v, ca); cb = fmaf(w3, u1v, cb);
        }
        float bt = bt1[k], bz = bzu1[k], bc = b1[k];
        u2a = fmaxf(ta + bt, 0.f);
        u2b = fmaxf(tb + bt, 0.f);
        u2s[0][k] = u2a; u2s[1][k] = u2b;
        g_gz1[n0 * DZ_ + k]       = fmaxf(za + bz, 0.f);
        g_gz1[(n0 + 1) * DZ_ + k] = fmaxf(zb + bz, 0.f);
        g_c1[n0 * DZ_ + k]        = ca + bc;
        g_c1[(n0 + 1) * DZ_ + k]  = cb + bc;
    }
    if (k < DY_) {
        #pragma unroll
        for (int nn = 0; nn < 2; ++nn) {
            float s0 = 0.f, s1 = 0.f;
            #pragma unroll 4
            for (int d = 0; d < DU_; d += 2) {
                s0 = fmaf(Wyu1[k * DU_ + d],     u1s[nn][d],     s0);
                s1 = fmaf(Wyu1[k * DU_ + d + 1], u1s[nn][d + 1], s1);
            }
            g_gy1[(n0 + nn) * DY_ + k] = s0 + s1 + byu1[k];
        }
    }
    __syncthreads();

    // ---- stage 3: gk2, w2d, c2 ----
    {
        float ga = 0.f, gb = 0.f;
        #pragma unroll 4
        for (int d = 0; d < DU_; ++d) {
            float w = g_WzuT2[d * 256 + k];
            ga = fmaf(w, u2s[0][d], ga);
            gb = fmaf(w, u2s[1][d], gb);
        }
        float bz = bzu2[k], sp = softplus_f(Wz2[k]);
        g_gk2[n0 * DZ_ + k]       = fmaxf(ga + bz, 0.f) * sp;
        g_gk2[(n0 + 1) * DZ_ + k] = fmaxf(gb + bz, 0.f) * sp;
    }
    if (k < DY_) {
        #pragma unroll
        for (int nn = 0; nn < 2; ++nn) {
            float s0 = 0.f, s1 = 0.f;
            #pragma unroll 4
            for (int d = 0; d < DU_; d += 2) {
                s0 = fmaf(Wyu2[k * DU_ + d],     u2s[nn][d],     s0);
                s1 = fmaf(Wyu2[k * DU_ + d + 1], u2s[nn][d + 1], s1);
            }
            g_w2d[(n0 + nn) * DY_ + k] = (s0 + s1 + byu2[k]) * Wy2[k];
        }
    }
    // c2 = u2 @ Wu2 + b2  (warp shuffles + tiny combine)
    {
        const int lane = k & 31, warp = k >> 5;
        float wv = Wu2[k];
        float p0 = u2a * wv, p1 = u2b * wv;
        #pragma unroll
        for (int off = 16; off; off >>= 1) {
            p0 += __shfl_xor_sync(0xffffffffu, p0, off);
            p1 += __shfl_xor_sync(0xffffffffu, p1, off);
        }
        if (lane == 0) { wred[0][warp] = p0; wred[1][warp] = p1; }
    }
    __syncthreads();
    if (k < 2) {
        float t = 0.f;
        #pragma unroll
        for (int w = 0; w < 8; ++w) t += wred[k][w];
        g_c2[n0 + k] = t + b2[0];
    }
}

// ---------------- kernel 2: fp16 HMMA GEMM + full phi + slack (R13, unchanged) ----------------
#define RS    144                   // row stride bytes
#define SM_W     0                  // 2 x 256*144 = 73728
#define SM_A     73728              // 2 x 64*144  = 18432
#define SM_WY0F  92160              // 256 x 12 floats = 12288
#define SM_C0    104448             // 256 floats
#define SM_GZ1   105472
#define SM_C1    106496
#define SM_GK2   107520
#define SM_GY1   108544             // 8 floats (pad 64B)
#define SM_YW    108608
#define SM_PHI   108672             // 256 floats
#define SMEM_BYTES 109696
#define WBUF  36864                 // 256*144
#define ABUF  9216                  // 64*144

extern __shared__ __align__(16) char smem[];

// fill one 64-z A chunk: thread owns row mrow, z quarter s (16 z)
__device__ __forceinline__ void fill_A64(char* Adst, int z0,
                                         const float* wy0f, const float* c0s,
                                         const float* gz1s, const float* ur,
                                         int mrow, int s)
{
    float o[16];
    #pragma unroll
    for (int jj = 0; jj < 16; ++jj) {
        const int j = (jj + s) & 15;           // bank-rotation schedule
        const int z = z0 + s * 16 + j;
        const float4 w0 = *(const float4*)(wy0f + z * 12);
        const float4 w1 = *(const float4*)(wy0f + z * 12 + 4);
        float v = c0s[z];
        v = fmaf(ur[0], w0.x, v); v = fmaf(ur[1], w0.y, v);
        v = fmaf(ur[2], w0.z, v); v = fmaf(ur[3], w0.w, v);
        v = fmaf(ur[4], w1.x, v); v = fmaf(ur[5], w1.y, v);
        v = fmaf(ur[6], w1.z, v); v = fmaf(ur[7], w1.w, v);
        o[j] = fmaxf(v, 0.f) * gz1s[z];
    }
    uint4 p0, p1;
    p0.x = pack_h2(o[0],  o[1]);  p0.y = pack_h2(o[2],  o[3]);
    p0.z = pack_h2(o[4],  o[5]);  p0.w = pack_h2(o[6],  o[7]);
    p1.x = pack_h2(o[8],  o[9]);  p1.y = pack_h2(o[10], o[11]);
    p1.z = pack_h2(o[12], o[13]); p1.w = pack_h2(o[14], o[15]);
    char* dst = Adst + mrow * RS + s * 32;
    *(uint4*)(dst)      = p0;
    *(uint4*)(dst + 16) = p1;
}

__global__ __launch_bounds__(256, 2) void main_mma_kernel(
    const float* __restrict__ U,
    const float* __restrict__ Y,
    const float* __restrict__ Wy0,
    const float* __restrict__ Wy1)
{
    const int tid  = threadIdx.x;
    const int lane = tid & 31;
    const int wid  = tid >> 5;
    const int g    = lane >> 2;     // groupID
    const int t4   = lane & 3;      // thread-in-group
    const int wm   = wid & 1;       // warp m-group (32 rows)
    const int wq   = wid >> 1;      // warp k-col group (64 cols)
    const int n    = blockIdx.y;
    const int m0   = blockIdx.x * 64;

    float* wy0f = (float*)(smem + SM_WY0F);
    float* c0s  = (float*)(smem + SM_C0);
    float* gz1s = (float*)(smem + SM_GZ1);
    float* c1s  = (float*)(smem + SM_C1);
    float* gk2s = (float*)(smem + SM_GK2);
    float* gy1s = (float*)(smem + SM_GY1);
    float* yws  = (float*)(smem + SM_YW);
    float* phiB = (float*)(smem + SM_PHI);
    const uint32_t sb = smem_u32(smem);

    // A-fill assignment
    const int mrow = tid >> 2;      // 0..63
    const int s    = tid & 3;       // z quarter

    // ldmatrix per-lane base addresses (buf 0)
    const int mi = lane >> 3, r = lane & 7;
    uint32_t a_base[2], b_base[4];
    #pragma unroll
    for (int i = 0; i < 2; ++i)
        a_base[i] = sb + SM_A + (uint32_t)((wm * 32 + i * 16 + (mi & 1) * 8 + r) * RS
                                           + (mi >> 1) * 16);
    #pragma unroll
    for (int jp = 0; jp < 4; ++jp)
        b_base[jp] = sb + SM_W + (uint32_t)((wq * 64 + jp * 16 + (mi >> 1) * 8 + r) * RS
                                            + (mi & 1) * 16);

    // ---- kick off W chunk 0 cp.async ----
    {
        const uint32_t Wdst = sb + SM_W;
        #pragma unroll
        for (int it = 0; it < 8; ++it) {
            int idx = it * 256 + tid;
            int q = idx >> 3, seg = idx & 7;
            CP_ASYNC16(Wdst + (uint32_t)(q * RS + seg * 16),
                       &g_sp1h[q * 256 + seg * 8]);
        }
        CP_COMMIT();
    }

    // ---- prologue: per-n consts ----
    c0s[tid]  = g_c0 [n * DZ_ + tid];
    gz1s[tid] = g_gz1[n * DZ_ + tid];
    c1s[tid]  = g_c1 [n * DZ_ + tid];
    gk2s[tid] = g_gk2[n * DZ_ + tid];
    if (tid < DY_) {
        gy1s[tid] = g_gy1[n * DY_ + tid];
        yws[tid]  = Y[n * DY_ + tid] - g_w2d[n * DY_ + tid];
    }
    {   // wy0f[z][d] = Wy0[z][d] * gy0[n][d], stride 12 floats
        const int z = tid;
        float4 wa = *(const float4*)&Wy0[z * 8];
        float4 wb = *(const float4*)&Wy0[z * 8 + 4];
        float4 ga = *(const float4*)&g_gy0[n * DY_];
        float4 gb = *(const float4*)&g_gy0[n * DY_ + 4];
        *(float4*)(wy0f + z * 12)     = make_float4(wa.x*ga.x, wa.y*ga.y, wa.z*ga.z, wa.w*ga.w);
        *(float4*)(wy0f + z * 12 + 4) = make_float4(wb.x*gb.x, wb.y*gb.y, wb.z*gb.z, wb.w*gb.w);
    }
    float ur[8];
    {
        float4 u0 = *(const float4*)&U[(m0 + mrow) * 8];
        float4 u1 = *(const float4*)&U[(m0 + mrow) * 8 + 4];
        ur[0]=u0.x; ur[1]=u0.y; ur[2]=u0.z; ur[3]=u0.w;
        ur[4]=u1.x; ur[5]=u1.y; ur[6]=u1.z; ur[7]=u1.w;
    }
    __syncthreads();

    fill_A64(smem + SM_A, 0, wy0f, c0s, gz1s, ur, mrow, s);
    CP_WAIT0();
    __syncthreads();

    float acc[2][8][4];
    #pragma unroll
    for (int i = 0; i < 2; ++i)
        #pragma unroll
        for (int j = 0; j < 8; ++j)
            #pragma unroll
            for (int q = 0; q < 4; ++q) acc[i][j][q] = 0.f;

    // ---- main loop: 4 real 64-z chunks + 1 pseudo k16 chunk ----
    #pragma unroll
    for (int c = 0; c < 5; ++c) {
        const int buf = c & 1, nb = buf ^ 1;

        if (c < 4) {
            if (c + 1 < 4) {
                const int z0n = (c + 1) * 64;
                const uint32_t Wdst = sb + SM_W + nb * WBUF;
                #pragma unroll
                for (int it = 0; it < 8; ++it) {
                    int idx = it * 256 + tid;
                    int q = idx >> 3, seg = idx & 7;
                    CP_ASYNC16(Wdst + (uint32_t)(q * RS + seg * 16),
                               &g_sp1h[q * 256 + z0n + seg * 8]);
                }
                CP_COMMIT();
                fill_A64(smem + SM_A + nb * ABUF, z0n, wy0f, c0s, gz1s, ur, mrow, s);
            } else {
                // pseudo chunk (k16): A[m][0..7]=U, 8..15=0; W[q][0..7]=Wy1*gy1
                char* Adst = smem + SM_A + nb * ABUF;
                if (s == 0) {
                    uint4 av, zv;
                    av.x = pack_h2(ur[0], ur[1]); av.y = pack_h2(ur[2], ur[3]);
                    av.z = pack_h2(ur[4], ur[5]); av.w = pack_h2(ur[6], ur[7]);
                    zv = make_uint4(0, 0, 0, 0);
                    *(uint4*)(Adst + mrow * RS)      = av;
                    *(uint4*)(Adst + mrow * RS + 16) = zv;
                }
                char* Wdst = smem + SM_W + nb * WBUF;
                const int q = tid;
                float4 w0 = *(const float4*)&Wy1[q * 8];
                float4 w1 = *(const float4*)&Wy1[q * 8 + 4];
                uint4 wv;
                wv.x = pack_h2(w0.x * gy1s[0], w0.y * gy1s[1]);
                wv.y = pack_h2(w0.z * gy1s[2], w0.w * gy1s[3]);
                wv.z = pack_h2(w1.x * gy1s[4], w1.y * gy1s[5]);
                wv.w = pack_h2(w1.z * gy1s[6], w1.w * gy1s[7]);
                *(uint4*)(Wdst + q * RS)      = wv;
                *(uint4*)(Wdst + q * RS + 16) = make_uint4(0, 0, 0, 0);
            }
        }

        // MMA on current buffer
        {
            const uint32_t aoff = buf * ABUF;
            const uint32_t woff = buf * WBUF;
            const int nks = (c == 4) ? 1 : 4;
            #pragma unroll
            for (int ks = 0; ks < 4; ++ks) {
                if (ks >= nks) break;
                const uint32_t kb = ks * 32;
                uint32_t a0[4], a1[4];
                LDSM_X4(a0[0], a0[1], a0[2], a0[3], a_base[0] + aoff + kb);
                LDSM_X4(a1[0], a1[1], a1[2], a1[3], a_base[1] + aoff + kb);
                #pragma unroll
                for (int jp = 0; jp < 4; ++jp) {
                    uint32_t b[4];
                    LDSM_X4(b[0], b[1], b[2], b[3], b_base[jp] + woff + kb);
                    mma_f16(acc[0][jp * 2],     a0, b[0], b[1]);
                    mma_f16(acc[1][jp * 2],     a1, b[0], b[1]);
                    mma_f16(acc[0][jp * 2 + 1], a0, b[2], b[3]);
                    mma_f16(acc[1][jp * 2 + 1], a1, b[2], b[3]);
                }
            }
        }
        if (c < 3) CP_WAIT0();
        __syncthreads();
    }

    // ---- epilogue: phi over this CTA's full 256 k ----
    float p[4] = {0.f, 0.f, 0.f, 0.f};
    #pragma unroll
    for (int j = 0; j < 8; ++j) {
        const int q = wq * 64 + j * 8 + 2 * t4;
        const float ca = c1s[q],  cb = c1s[q + 1];
        const float ga = gk2s[q], gb = gk2s[q + 1];
        #pragma unroll
        for (int i = 0; i < 2; ++i) {
            p[i*2+0] = fmaf(fmaxf(acc[i][j][0] + ca, 0.f), ga, p[i*2+0]);
            p[i*2+0] = fmaf(fmaxf(acc[i][j][1] + cb, 0.f), gb, p[i*2+0]);
            p[i*2+1] = fmaf(fmaxf(acc[i][j][2] + ca, 0.f), ga, p[i*2+1]);
            p[i*2+1] = fmaf(fmaxf(acc[i][j][3] + cb, 0.f), gb, p[i*2+1]);
        }
    }
    #pragma unroll
    for (int idx = 0; idx < 4; ++idx) {
        float v = p[idx];
        v += __shfl_xor_sync(0xffffffffu, v, 1);
        v += __shfl_xor_sync(0xffffffffu, v, 2);
        if (t4 == 0) {
            const int i = idx >> 1, h = idx & 1;
            phiB[wq * 64 + wm * 32 + i * 16 + h * 8 + g] = v;
        }
    }
    __syncthreads();
    if (tid < 64) {
        float phi = phiB[tid] + phiB[64 + tid] + phiB[128 + tid] + phiB[192 + tid];
        float4 u0 = *(const float4*)&U[(m0 + tid) * 8];
        float4 u1 = *(const float4*)&U[(m0 + tid) * 8 + 4];
        float sl = -g_c2[n] - phi;
        sl = fmaf(u0.x, yws[0], sl); sl = fmaf(u0.y, yws[1], sl);
        sl = fmaf(u0.z, yws[2], sl); sl = fmaf(u0.w, yws[3], sl);
        sl = fmaf(u1.x, yws[4], sl); sl = fmaf(u1.y, yws[5], sl);
        sl = fmaf(u1.z, yws[6], sl); sl = fmaf(u1.w, yws[7], sl);
        g_slack[n * M_ + m0 + tid] = sl;
    }
}

// ---------------- kernel 3: row-wise stable logsumexp ----------------
__global__ void lse_kernel(float* __restrict__ out) {
    __shared__ float wred[8];
    __shared__ float bmax_s;
    const int n = blockIdx.x, tid = threadIdx.x;
    const int lane = tid & 31, warp = tid >> 5;

    float s[8];
    #pragma unroll
    for (int i = 0; i < 8; i++) s[i] = g_slack[n * M_ + tid + i * 256];

    float mx = s[0];
    #pragma unroll
    for (int i = 1; i < 8; i++) mx = fmaxf(mx, s[i]);
    #pragma unroll
    for (int off = 16; off; off >>= 1)
        mx = fmaxf(mx, __shfl_xor_sync(0xffffffffu, mx, off));
    if (lane == 0) wred[warp] = mx;
    __syncthreads();
    if (tid == 0) {
        float m2 = wred[0];
        #pragma unroll
        for (int w = 1; w < 8; w++) m2 = fmaxf(m2, wred[w]);
        bmax_s = m2;
    }
    __syncthreads();
    const float bmax = bmax_s;

    float sum = 0.f;
    #pragma unroll
    for (int i = 0; i < 8; i++) sum += expf((s[i] - bmax) * 100.f);
    #pragma unroll
    for (int off = 16; off; off >>= 1)
        sum += __shfl_xor_sync(0xffffffffu, sum, off);
    __syncthreads();
    if (lane == 0) wred[warp] = sum;
    __syncthreads();
    if (tid == 0) {
        float tot = 0.f;
        #pragma unroll
        for (int w = 0; w < 8; w++) tot += wred[w];
        out[n] = 0.01f * (logf(tot) - logf(2048.0f)) + bmax;
    }
}

// ---------------- launch ----------------
extern "C" void kernel_launch(void* const* d_in, const int* in_sizes, int n_in,
                              void* d_out, int out_size) {
    const float* X    = (const float*)d_in[0];
    const float* U    = (const float*)d_in[1];
    const float* Y    = (const float*)d_in[2];
    const float* Wt0  = (const float*)d_in[3];
    const float* bt0  = (const float*)d_in[4];
    const float* Wt1  = (const float*)d_in[5];
    const float* bt1  = (const float*)d_in[6];
    const float* Wyu0 = (const float*)d_in[7];
    const float* byu0 = (const float*)d_in[8];
    const float* Wy0  = (const float*)d_in[9];
    const float* Wu0  = (const float*)d_in[10];
    const float* b0   = (const float*)d_in[11];
    const float* Wzu1 = (const float*)d_in[12];
    const float* bzu1 = (const float*)d_in[13];
    const float* Wz1  = (const float*)d_in[14];
    const float* Wyu1 = (const float*)d_in[15];
    const float* byu1 = (const float*)d_in[16];
    const float* Wy1  = (const float*)d_in[17];
    const float* Wu1  = (const float*)d_in[18];
    const float* b1   = (const float*)d_in[19];
    const float* Wzu2 = (const float*)d_in[20];
    const float* bzu2 = (const float*)d_in[21];
    const float* Wz2  = (const float*)d_in[22];
    const float* Wyu2 = (const float*)d_in[23];
    const float* byu2 = (const float*)d_in[24];
    const float* Wy2  = (const float*)d_in[25];
    const float* Wu2  = (const float*)d_in[26];
    const float* b2   = (const float*)d_in[27];

    cudaFuncSetAttribute(main_mma_kernel,
                         cudaFuncAttributeMaxDynamicSharedMemorySize, SMEM_BYTES);

    sp1_kernel<<<256, 256>>>(Wz1);
    {
        dim3 blk(32, 8);
        tr256_kernel<<<dim3(8, 8, 4), blk>>>(Wt1, Wzu1, Wu1, Wzu2);
        tr64_kernel<<<dim3(2, 8, 2), blk>>>(Wt0, Wu0);
    }
    setup_kernel<<<64, 256>>>(X, bt0, bt1, Wyu0, byu0, b0,
                              bzu1, Wyu1, byu1, b1,
                              bzu2, Wz2, Wyu2, byu2, Wy2, Wu2, b2);
    dim3 grid(32, 128);
    main_mma_kernel<<<grid, 256, SMEM_BYTES>>>(U, Y, Wy0, Wy1);
    lse_kernel<<<128, 256>>>((float*)d_out);
}

// round 16
// speedup vs baseline: 1.1230x; 1.1230x over previous
#include <cuda_runtime.h>
#include <cuda_fp16.h>
#include <math.h>
#include <stdint.h>

// Problem dims
#define N_  128
#define M_  2048
#define DX_ 64
#define DY_ 8
#define DU_ 256
#define DZ_ 256

// ---------------- device scratch (static, no allocations) ----------------
__device__ __align__(16) __half g_sp1h[DZ_ * DZ_];  // fp16(softplus(Wz1)) [k][z]
__device__ __align__(16) float g_u1T[DU_ * N_];     // u1 transposed [d][n]
__device__ __align__(16) float g_u2T[DU_ * N_];     // u2 transposed [d][n]
__device__ __align__(16) float g_gy0[N_ * DY_];
__device__ __align__(16) float g_c0 [N_ * DZ_];
__device__ __align__(16) float g_gz1[N_ * DZ_];
__device__ __align__(16) float g_gy1[N_ * DY_];
__device__ __align__(16) float g_c1 [N_ * DZ_];
__device__ __align__(16) float g_gk2[N_ * DZ_];     // gz2 * softplus(Wz2)
__device__ __align__(16) float g_w2d[N_ * DY_];     // gy2 * Wy2
__device__ __align__(16) float g_c2 [N_];
__device__ __align__(16) float g_slack[N_ * M_];

__device__ __forceinline__ float softplus_f(float x) {
    return fmaxf(x, 0.f) + log1pf(expf(-fabsf(x)));
}

#define CP_ASYNC16(dst, src) \
    asm volatile("cp.async.cg.shared.global [%0], [%1], 16;" \
        :: "r"((uint32_t)(dst)), "l"(src) : "memory")
#define CP_COMMIT() asm volatile("cp.async.commit_group;" ::: "memory")
#define CP_WAIT0()  asm volatile("cp.async.wait_group 0;" ::: "memory")

__device__ __forceinline__ uint32_t smem_u32(const void* p) {
    uint32_t a;
    asm("{ .reg .u64 t; cvta.to.shared.u64 t, %1; cvt.u32.u64 %0, t; }"
        : "=r"(a) : "l"(p));
    return a;
}

// m16n8k16 fp16 MMA, fp32 accumulate
__device__ __forceinline__ void mma_f16(float* c, const uint32_t* a,
                                        uint32_t b0, uint32_t b1) {
    asm volatile(
        "mma.sync.aligned.m16n8k16.row.col.f32.f16.f16.f32 "
        "{%0,%1,%2,%3}, {%4,%5,%6,%7}, {%8,%9}, {%0,%1,%2,%3};"
        : "+f"(c[0]), "+f"(c[1]), "+f"(c[2]), "+f"(c[3])
        : "r"(a[0]), "r"(a[1]), "r"(a[2]), "r"(a[3]), "r"(b0), "r"(b1));
}

#define LDSM_X4(r0, r1, r2, r3, addr) \
    asm volatile("ldmatrix.sync.aligned.m8n8.x4.shared.b16 {%0,%1,%2,%3}, [%4];" \
        : "=r"(r0), "=r"(r1), "=r"(r2), "=r"(r3) : "r"(addr))

__device__ __forceinline__ uint32_t pack_h2(float lo, float hi) {
    __half2 h = __floats2half2_rn(lo, hi);
    return *(uint32_t*)&h;
}

// ---------------- kernel 0: fp16(softplus(Wz1)) ----------------
__global__ void sp1_kernel(const float* __restrict__ Wz1) {
    int i = blockIdx.x * 256 + threadIdx.x;
    g_sp1h[i] = __float2half_rn(softplus_f(Wz1[i]));
}

// ---------------- stage A: X -> u1T (relu), c0 ----------------
// grid 16: kt = x&7 (32-out tile), mt = x>>3 (0: u1T, 1: c0). 256 thr.
__global__ __launch_bounds__(256) void stageA_kernel(
    const float* __restrict__ X,
    const float* __restrict__ Wt0, const float* __restrict__ bt0,
    const float* __restrict__ Wu0, const float* __restrict__ b0)
{
    __shared__ float As[64][128];   // X^T  [d][n]
    __shared__ float Ws[32][68];
    const int tid = threadIdx.x;
    const int kt  = blockIdx.x & 7;
    const int mt  = blockIdx.x >> 3;
    const float* W = mt ? Wu0 : Wt0;
    const int k  = tid >> 3;        // 0..31
    const int q  = tid & 7;
    const int n0 = q * 16;
    const int kg = kt * 32 + k;

    // stage X transposed: thread owns row n = tid>>1, half = tid&1 (32 d)
    {
        const int n = tid >> 1, half = tid & 1;
        #pragma unroll
        for (int j = 0; j < 8; ++j) {
            const int c = half * 32 + j * 4;
            float4 f = *(const float4*)&X[n * DX_ + c];
            As[c + 0][n] = f.x; As[c + 1][n] = f.y;
            As[c + 2][n] = f.z; As[c + 3][n] = f.w;
        }
    }
    // stage W tile [32 k][64 d]
    {
        const int k2 = tid >> 3, seg = tid & 7;
        *(float4*)&Ws[k2][seg * 4]      = *(const float4*)&W[(kt * 32 + k2) * DX_ + seg * 4];
        *(float4*)&Ws[k2][32 + seg * 4] = *(const float4*)&W[(kt * 32 + k2) * DX_ + 32 + seg * 4];
    }
    __syncthreads();

    float acc[16];
    #pragma unroll
    for (int i = 0; i < 16; ++i) acc[i] = 0.f;

    #pragma unroll 8
    for (int d = 0; d < DX_; ++d) {
        const float w = Ws[k][d];
        float4 a0 = *(const float4*)&As[d][n0];
        float4 a1 = *(const float4*)&As[d][n0 + 4];
        float4 a2 = *(const float4*)&As[d][n0 + 8];
        float4 a3 = *(const float4*)&As[d][n0 + 12];
        acc[0]  = fmaf(w, a0.x, acc[0]);  acc[1]  = fmaf(w, a0.y, acc[1]);
        acc[2]  = fmaf(w, a0.z, acc[2]);  acc[3]  = fmaf(w, a0.w, acc[3]);
        acc[4]  = fmaf(w, a1.x, acc[4]);  acc[5]  = fmaf(w, a1.y, acc[5]);
        acc[6]  = fmaf(w, a1.z, acc[6]);  acc[7]  = fmaf(w, a1.w, acc[7]);
        acc[8]  = fmaf(w, a2.x, acc[8]);  acc[9]  = fmaf(w, a2.y, acc[9]);
        acc[10] = fmaf(w, a2.z, acc[10]); acc[11] = fmaf(w, a2.w, acc[11]);
        acc[12] = fmaf(w, a3.x, acc[12]); acc[13] = fmaf(w, a3.y, acc[13]);
        acc[14] = fmaf(w, a3.z, acc[14]); acc[15] = fmaf(w, a3.w, acc[15]);
    }

    if (mt == 0) {
        const float b = bt0[kg];
        #pragma unroll
        for (int j = 0; j < 4; ++j) {
            float4 o;
            o.x = fmaxf(acc[j*4+0] + b, 0.f); o.y = fmaxf(acc[j*4+1] + b, 0.f);
            o.z = fmaxf(acc[j*4+2] + b, 0.f); o.w = fmaxf(acc[j*4+3] + b, 0.f);
            *(float4*)&g_u1T[kg * N_ + n0 + j * 4] = o;
        }
    } else {
        const float b = b0[kg];
        #pragma unroll
        for (int i = 0; i < 16; ++i)
            g_c0[(n0 + i) * DZ_ + kg] = acc[i] + b;
    }
}

// ---------------- stage B: u1T -> u2T (relu), gz1 (relu), c1 ----------------
// grid 48: kt = x&15 (16-out tile), mt = x>>4 (0: u2T, 1: gz1, 2: c1). 256 thr.
__global__ __launch_bounds__(256) void stageB_kernel(
    const float* __restrict__ Wt1,  const float* __restrict__ bt1,
    const float* __restrict__ Wzu1, const float* __restrict__ bzu1,
    const float* __restrict__ Wu1,  const float* __restrict__ b1)
{
    __shared__ float Ws[16][36];
    __shared__ float As[32][128];
    const int tid = threadIdx.x;
    const int kt  = blockIdx.x & 15;
    const int mt  = blockIdx.x >> 4;
    const float* W = (mt == 0) ? Wt1 : (mt == 1 ? Wzu1 : Wu1);
    const int k  = tid >> 4;        // 0..15
    const int q  = tid & 15;
    const int n0 = q * 8;
    const int kg = kt * 16 + k;

    float acc[8] = {0.f, 0.f, 0.f, 0.f, 0.f, 0.f, 0.f, 0.f};

    for (int dc = 0; dc < DU_; dc += 32) {
        if (tid < 128) {
            const int k2 = tid >> 3, seg = tid & 7;
            *(float4*)&Ws[k2][seg * 4] =
                *(const float4*)&W[(kt * 16 + k2) * DU_ + dc + seg * 4];
        }
        {
            const int row = tid >> 3, c0 = (tid & 7) * 16;
            const float4* src = (const float4*)&g_u1T[(dc + row) * N_ + c0];
            float4* dst = (float4*)&As[row][c0];
            dst[0] = src[0]; dst[1] = src[1]; dst[2] = src[2]; dst[3] = src[3];
        }
        __syncthreads();
        #pragma unroll
        for (int d = 0; d < 32; ++d) {
            const float w = Ws[k][d];
            float4 a0 = *(const float4*)&As[d][n0];
            float4 a1 = *(const float4*)&As[d][n0 + 4];
            acc[0] = fmaf(w, a0.x, acc[0]); acc[1] = fmaf(w, a0.y, acc[1]);
            acc[2] = fmaf(w, a0.z, acc[2]); acc[3] = fmaf(w, a0.w, acc[3]);
            acc[4] = fmaf(w, a1.x, acc[4]); acc[5] = fmaf(w, a1.y, acc[5]);
            acc[6] = fmaf(w, a1.z, acc[6]); acc[7] = fmaf(w, a1.w, acc[7]);
        }
        __syncthreads();
    }

    if (mt == 0) {
        const float b = bt1[kg];
        float4 o0, o1;
        o0.x = fmaxf(acc[0] + b, 0.f); o0.y = fmaxf(acc[1] + b, 0.f);
        o0.z = fmaxf(acc[2] + b, 0.f); o0.w = fmaxf(acc[3] + b, 0.f);
        o1.x = fmaxf(acc[4] + b, 0.f); o1.y = fmaxf(acc[5] + b, 0.f);
        o1.z = fmaxf(acc[6] + b, 0.f); o1.w = fmaxf(acc[7] + b, 0.f);
        *(float4*)&g_u2T[kg * N_ + n0]     = o0;
        *(float4*)&g_u2T[kg * N_ + n0 + 4] = o1;
    } else if (mt == 1) {
        const float b = bzu1[kg];
        #pragma unroll
        for (int i = 0; i < 8; ++i)
            g_gz1[(n0 + i) * DZ_ + kg] = fmaxf(acc[i] + b, 0.f);
    } else {
        const float b = b1[kg];
        #pragma unroll
        for (int i = 0; i < 8; ++i)
            g_c1[(n0 + i) * DZ_ + kg] = acc[i] + b;
    }
}

// ---------------- stage C: u2T -> gk2 ----------------
// grid 16: kt (16-out tile). 256 thr.
__global__ __launch_bounds__(256) void stageC_kernel(
    const float* __restrict__ Wzu2, const float* __restrict__ bzu2,
    const float* __restrict__ Wz2)
{
    __shared__ float Ws[16][36];
    __shared__ float As[32][128];
    const int tid = threadIdx.x;
    const int kt  = blockIdx.x;
    const int k  = tid >> 4;
    const int q  = tid & 15;
    const int n0 = q * 8;
    const int kg = kt * 16 + k;

    float acc[8] = {0.f, 0.f, 0.f, 0.f, 0.f, 0.f, 0.f, 0.f};

    for (int dc = 0; dc < DU_; dc += 32) {
        if (tid < 128) {
            const int k2 = tid >> 3, seg = tid & 7;
            *(float4*)&Ws[k2][seg * 4] =
                *(const float4*)&Wzu2[(kt * 16 + k2) * DU_ + dc + seg * 4];
        }
        {
            const int row = tid >> 3, c0 = (tid & 7) * 16;
            const float4* src = (const float4*)&g_u2T[(dc + row) * N_ + c0];
            float4* dst = (float4*)&As[row][c0];
            dst[0] = src[0]; dst[1] = src[1]; dst[2] = src[2]; dst[3] = src[3];
        }
        __syncthreads();
        #pragma unroll
        for (int d = 0; d < 32; ++d) {
            const float w = Ws[k][d];
            float4 a0 = *(const float4*)&As[d][n0];
            float4 a1 = *(const float4*)&As[d][n0 + 4];
            acc[0] = fmaf(w, a0.x, acc[0]); acc[1] = fmaf(w, a0.y, acc[1]);
            acc[2] = fmaf(w, a0.z, acc[2]); acc[3] = fmaf(w, a0.w, acc[3]);
            acc[4] = fmaf(w, a1.x, acc[4]); acc[5] = fmaf(w, a1.y, acc[5]);
            acc[6] = fmaf(w, a1.z, acc[6]); acc[7] = fmaf(w, a1.w, acc[7]);
        }
        __syncthreads();
    }

    const float b = bzu2[kg];
    const float sp = softplus_f(Wz2[kg]);
    #pragma unroll
    for (int i = 0; i < 8; ++i)
        g_gk2[(n0 + i) * DZ_ + kg] = fmaxf(acc[i] + b, 0.f) * sp;
}

// ---------------- smalls: gy0, gy1, w2d, c2 ----------------
// grid 128 (one n per CTA), 256 thr (8 warps; warp w handles output k=w).
__global__ __launch_bounds__(256) void smalls_kernel(
    const float* __restrict__ X,
    const float* __restrict__ Wyu0, const float* __restrict__ byu0,
    const float* __restrict__ Wyu1, const float* __restrict__ byu1,
    const float* __restrict__ Wyu2, const float* __restrict__ byu2,
    const float* __restrict__ Wy2,
    const float* __restrict__ Wu2,  const float* __restrict__ b2)
{
    const int n = blockIdx.x;
    const int tid = threadIdx.x;
    const int wid = tid >> 5, lane = tid & 31;

    // gy0: in-dim 64 on X
    {
        float s = 0.f;
        #pragma unroll
        for (int d = lane; d < DX_; d += 32)
            s = fmaf(X[n * DX_ + d], Wyu0[wid * DX_ + d], s);
        #pragma unroll
        for (int off = 16; off; off >>= 1) s += __shfl_xor_sync(0xffffffffu, s, off);
        if (lane == 0) g_gy0[n * DY_ + wid] = s + byu0[wid];
    }
    // gy1: in-dim 256 on u1T
    {
        float s = 0.f;
        #pragma unroll
        for (int d = lane; d < DU_; d += 32)
            s = fmaf(g_u1T[d * N_ + n], Wyu1[wid * DU_ + d], s);
        #pragma unroll
        for (int off = 16; off; off >>= 1) s += __shfl_xor_sync(0xffffffffu, s, off);
        if (lane == 0) g_gy1[n * DY_ + wid] = s + byu1[wid];
    }
    // w2d: in-dim 256 on u2T, scaled by Wy2
    {
        float s = 0.f;
        #pragma unroll
        for (int d = lane; d < DU_; d += 32)
            s = fmaf(g_u2T[d * N_ + n], Wyu2[wid * DU_ + d], s);
        #pragma unroll
        for (int off = 16; off; off >>= 1) s += __shfl_xor_sync(0xffffffffu, s, off);
        if (lane == 0) g_w2d[n * DY_ + wid] = (s + byu2[wid]) * Wy2[wid];
    }
    // c2: warp 0
    if (wid == 0) {
        float s = 0.f;
        #pragma unroll
        for (int d = lane; d < DU_; d += 32)
            s = fmaf(g_u2T[d * N_ + n], Wu2[d], s);
        #pragma unroll
        for (int off = 16; off; off >>= 1) s += __shfl_xor_sync(0xffffffffu, s, off);
        if (lane == 0) g_c2[n] = s + b2[0];
    }
}

// ---------------- kernel 2: fp16 HMMA GEMM + full phi + slack (R13, unchanged) ----------------
#define RS    144                   // row stride bytes
#define SM_W     0                  // 2 x 256*144 = 73728
#define SM_A     73728              // 2 x 64*144  = 18432
#define SM_WY0F  92160              // 256 x 12 floats = 12288
#define SM_C0    104448             // 256 floats
#define SM_GZ1   105472
#define SM_C1    106496
#define SM_GK2   107520
#define SM_GY1   108544             // 8 floats (pad 64B)
#define SM_YW    108608
#define SM_PHI   108672             // 256 floats
#define SMEM_BYTES 109696
#define WBUF  36864                 // 256*144
#define ABUF  9216                  // 64*144

extern __shared__ __align__(16) char smem[];

// fill one 64-z A chunk: thread owns row mrow, z quarter s (16 z)
__device__ __forceinline__ void fill_A64(char* Adst, int z0,
                                         const float* wy0f, const float* c0s,
                                         const float* gz1s, const float* ur,
                                         int mrow, int s)
{
    float o[16];
    #pragma unroll
    for (int jj = 0; jj < 16; ++jj) {
        const int j = (jj + s) & 15;           // bank-rotation schedule
        const int z = z0 + s * 16 + j;
        const float4 w0 = *(const float4*)(wy0f + z * 12);
        const float4 w1 = *(const float4*)(wy0f + z * 12 + 4);
        float v = c0s[z];
        v = fmaf(ur[0], w0.x, v); v = fmaf(ur[1], w0.y, v);
        v = fmaf(ur[2], w0.z, v); v = fmaf(ur[3], w0.w, v);
        v = fmaf(ur[4], w1.x, v); v = fmaf(ur[5], w1.y, v);
        v = fmaf(ur[6], w1.z, v); v = fmaf(ur[7], w1.w, v);
        o[j] = fmaxf(v, 0.f) * gz1s[z];
    }
    uint4 p0, p1;
    p0.x = pack_h2(o[0],  o[1]);  p0.y = pack_h2(o[2],  o[3]);
    p0.z = pack_h2(o[4],  o[5]);  p0.w = pack_h2(o[6],  o[7]);
    p1.x = pack_h2(o[8],  o[9]);  p1.y = pack_h2(o[10], o[11]);
    p1.z = pack_h2(o[12], o[13]); p1.w = pack_h2(o[14], o[15]);
    char* dst = Adst + mrow * RS + s * 32;
    *(uint4*)(dst)      = p0;
    *(uint4*)(dst + 16) = p1;
}

__global__ __launch_bounds__(256, 2) void main_mma_kernel(
    const float* __restrict__ U,
    const float* __restrict__ Y,
    const float* __restrict__ Wy0,
    const float* __restrict__ Wy1)
{
    const int tid  = threadIdx.x;
    const int lane = tid & 31;
    const int wid  = tid >> 5;
    const int g    = lane >> 2;     // groupID
    const int t4   = lane & 3;      // thread-in-group
    const int wm   = wid & 1;       // warp m-group (32 rows)
    const int wq   = wid >> 1;      // warp k-col group (64 cols)
    const int n    = blockIdx.y;
    const int m0   = blockIdx.x * 64;

    float* wy0f = (float*)(smem + SM_WY0F);
    float* c0s  = (float*)(smem + SM_C0);
    float* gz1s = (float*)(smem + SM_GZ1);
    float* c1s  = (float*)(smem + SM_C1);
    float* gk2s = (float*)(smem + SM_GK2);
    float* gy1s = (float*)(smem + SM_GY1);
    float* yws  = (float*)(smem + SM_YW);
    float* phiB = (float*)(smem + SM_PHI);
    const uint32_t sb = smem_u32(smem);

    // A-fill assignment
    const int mrow = tid >> 2;      // 0..63
    const int s    = tid & 3;       // z quarter

    // ldmatrix per-lane base addresses (buf 0)
    const int mi = lane >> 3, r = lane & 7;
    uint32_t a_base[2], b_base[4];
    #pragma unroll
    for (int i = 0; i < 2; ++i)
        a_base[i] = sb + SM_A + (uint32_t)((wm * 32 + i * 16 + (mi & 1) * 8 + r) * RS
                                           + (mi >> 1) * 16);
    #pragma unroll
    for (int jp = 0; jp < 4; ++jp)
        b_base[jp] = sb + SM_W + (uint32_t)((wq * 64 + jp * 16 + (mi >> 1) * 8 + r) * RS
                                            + (mi & 1) * 16);

    // ---- kick off W chunk 0 cp.async ----
    {
        const uint32_t Wdst = sb + SM_W;
        #pragma unroll
        for (int it = 0; it < 8; ++it) {
            int idx = it * 256 + tid;
            int q = idx >> 3, seg = idx & 7;
            CP_ASYNC16(Wdst + (uint32_t)(q * RS + seg * 16),
                       &g_sp1h[q * 256 + seg * 8]);
        }
        CP_COMMIT();
    }

    // ---- prologue: per-n consts ----
    c0s[tid]  = g_c0 [n * DZ_ + tid];
    gz1s[tid] = g_gz1[n * DZ_ + tid];
    c1s[tid]  = g_c1 [n * DZ_ + tid];
    gk2s[tid] = g_gk2[n * DZ_ + tid];
    if (tid < DY_) {
        gy1s[tid] = g_gy1[n * DY_ + tid];
        yws[tid]  = Y[n * DY_ + tid] - g_w2d[n * DY_ + tid];
    }
    {   // wy0f[z][d] = Wy0[z][d] * gy0[n][d], stride 12 floats
        const int z = tid;
        float4 wa = *(const float4*)&Wy0[z * 8];
        float4 wb = *(const float4*)&Wy0[z * 8 + 4];
        float4 ga = *(const float4*)&g_gy0[n * DY_];
        float4 gb = *(const float4*)&g_gy0[n * DY_ + 4];
        *(float4*)(wy0f + z * 12)     = make_float4(wa.x*ga.x, wa.y*ga.y, wa.z*ga.z, wa.w*ga.w);
        *(float4*)(wy0f + z * 12 + 4) = make_float4(wb.x*gb.x, wb.y*gb.y, wb.z*gb.z, wb.w*gb.w);
    }
    float ur[8];
    {
        float4 u0 = *(const float4*)&U[(m0 + mrow) * 8];
        float4 u1 = *(const float4*)&U[(m0 + mrow) * 8 + 4];
        ur[0]=u0.x; ur[1]=u0.y; ur[2]=u0.z; ur[3]=u0.w;
        ur[4]=u1.x; ur[5]=u1.y; ur[6]=u1.z; ur[7]=u1.w;
    }
    __syncthreads();

    fill_A64(smem + SM_A, 0, wy0f, c0s, gz1s, ur, mrow, s);
    CP_WAIT0();
    __syncthreads();

    float acc[2][8][4];
    #pragma unroll
    for (int i = 0; i < 2; ++i)
        #pragma unroll
        for (int j = 0; j < 8; ++j)
            #pragma unroll
            for (int q = 0; q < 4; ++q) acc[i][j][q] = 0.f;

    // ---- main loop: 4 real 64-z chunks + 1 pseudo k16 chunk ----
    #pragma unroll
    for (int c = 0; c < 5; ++c) {
        const int buf = c & 1, nb = buf ^ 1;

        if (c < 4) {
            if (c + 1 < 4) {
                const int z0n = (c + 1) * 64;
                const uint32_t Wdst = sb + SM_W + nb * WBUF;
                #pragma unroll
                for (int it = 0; it < 8; ++it) {
                    int idx = it * 256 + tid;
                    int q = idx >> 3, seg = idx & 7;
                    CP_ASYNC16(Wdst + (uint32_t)(q * RS + seg * 16),
                               &g_sp1h[q * 256 + z0n + seg * 8]);
                }
                CP_COMMIT();
                fill_A64(smem + SM_A + nb * ABUF, z0n, wy0f, c0s, gz1s, ur, mrow, s);
            } else {
                // pseudo chunk (k16): A[m][0..7]=U, 8..15=0; W[q][0..7]=Wy1*gy1
                char* Adst = smem + SM_A + nb * ABUF;
                if (s == 0) {
                    uint4 av, zv;
                    av.x = pack_h2(ur[0], ur[1]); av.y = pack_h2(ur[2], ur[3]);
                    av.z = pack_h2(ur[4], ur[5]); av.w = pack_h2(ur[6], ur[7]);
                    zv = make_uint4(0, 0, 0, 0);
                    *(uint4*)(Adst + mrow * RS)      = av;
                    *(uint4*)(Adst + mrow * RS + 16) = zv;
                }
                char* Wdst = smem + SM_W + nb * WBUF;
                const int q = tid;
                float4 w0 = *(const float4*)&Wy1[q * 8];
                float4 w1 = *(const float4*)&Wy1[q * 8 + 4];
                uint4 wv;
                wv.x = pack_h2(w0.x * gy1s[0], w0.y * gy1s[1]);
                wv.y = pack_h2(w0.z * gy1s[2], w0.w * gy1s[3]);
                wv.z = pack_h2(w1.x * gy1s[4], w1.y * gy1s[5]);
                wv.w = pack_h2(w1.z * gy1s[6], w1.w * gy1s[7]);
                *(uint4*)(Wdst + q * RS)      = wv;
                *(uint4*)(Wdst + q * RS + 16) = make_uint4(0, 0, 0, 0);
            }
        }

        // MMA on current buffer
        {
            const uint32_t aoff = buf * ABUF;
            const uint32_t woff = buf * WBUF;
            const int nks = (c == 4) ? 1 : 4;
            #pragma unroll
            for (int ks = 0; ks < 4; ++ks) {
                if (ks >= nks) break;
                const uint32_t kb = ks * 32;
                uint32_t a0[4], a1[4];
                LDSM_X4(a0[0], a0[1], a0[2], a0[3], a_base[0] + aoff + kb);
                LDSM_X4(a1[0], a1[1], a1[2], a1[3], a_base[1] + aoff + kb);
                #pragma unroll
                for (int jp = 0; jp < 4; ++jp) {
                    uint32_t b[4];
                    LDSM_X4(b[0], b[1], b[2], b[3], b_base[jp] + woff + kb);
                    mma_f16(acc[0][jp * 2],     a0, b[0], b[1]);
                    mma_f16(acc[1][jp * 2],     a1, b[0], b[1]);
                    mma_f16(acc[0][jp * 2 + 1], a0, b[2], b[3]);
                    mma_f16(acc[1][jp * 2 + 1], a1, b[2], b[3]);
                }
            }
        }
        if (c < 3) CP_WAIT0();
        __syncthreads();
    }

    // ---- epilogue: phi over this CTA's full 256 k ----
    float p[4] = {0.f, 0.f, 0.f, 0.f};
    #pragma unroll
    for (int j = 0; j < 8; ++j) {
        const int q = wq * 64 + j * 8 + 2 * t4;
        const float ca = c1s[q],  cb = c1s[q + 1];
        const float ga = gk2s[q], gb = gk2s[q + 1];
        #pragma unroll
        for (int i = 0; i < 2; ++i) {
            p[i*2+0] = fmaf(fmaxf(acc[i][j][0] + ca, 0.f), ga, p[i*2+0]);
            p[i*2+0] = fmaf(fmaxf(acc[i][j][1] + cb, 0.f), gb, p[i*2+0]);
            p[i*2+1] = fmaf(fmaxf(acc[i][j][2] + ca, 0.f), ga, p[i*2+1]);
            p[i*2+1] = fmaf(fmaxf(acc[i][j][3] + cb, 0.f), gb, p[i*2+1]);
        }
    }
    #pragma unroll
    for (int idx = 0; idx < 4; ++idx) {
        float v = p[idx];
        v += __shfl_xor_sync(0xffffffffu, v, 1);
        v += __shfl_xor_sync(0xffffffffu, v, 2);
        if (t4 == 0) {
            const int i = idx >> 1, h = idx & 1;
            phiB[wq * 64 + wm * 32 + i * 16 + h * 8 + g] = v;
        }
    }
    __syncthreads();
    if (tid < 64) {
        float phi = phiB[tid] + phiB[64 + tid] + phiB[128 + tid] + phiB[192 + tid];
        float4 u0 = *(const float4*)&U[(m0 + tid) * 8];
        float4 u1 = *(const float4*)&U[(m0 + tid) * 8 + 4];
        float sl = -g_c2[n] - phi;
        sl = fmaf(u0.x, yws[0], sl); sl = fmaf(u0.y, yws[1], sl);
        sl = fmaf(u0.z, yws[2], sl); sl = fmaf(u0.w, yws[3], sl);
        sl = fmaf(u1.x, yws[4], sl); sl = fmaf(u1.y, yws[5], sl);
        sl = fmaf(u1.z, yws[6], sl); sl = fmaf(u1.w, yws[7], sl);
        g_slack[n * M_ + m0 + tid] = sl;
    }
}

// ---------------- kernel 3: row-wise stable logsumexp ----------------
__global__ void lse_kernel(float* __restrict__ out) {
    __shared__ float wred[8];
    __shared__ float bmax_s;
    const int n = blockIdx.x, tid = threadIdx.x;
    const int lane = tid & 31, warp = tid >> 5;

    float s[8];
    #pragma unroll
    for (int i = 0; i < 8; i++) s[i] = g_slack[n * M_ + tid + i * 256];

    float mx = s[0];
    #pragma unroll
    for (int i = 1; i < 8; i++) mx = fmaxf(mx, s[i]);
    #pragma unroll
    for (int off = 16; off; off >>= 1)
        mx = fmaxf(mx, __shfl_xor_sync(0xffffffffu, mx, off));
    if (lane == 0) wred[warp] = mx;
    __syncthreads();
    if (tid == 0) {
        float m2 = wred[0];
        #pragma unroll
        for (int w = 1; w < 8; w++) m2 = fmaxf(m2, wred[w]);
        bmax_s = m2;
    }
    __syncthreads();
    const float bmax = bmax_s;

    float sum = 0.f;
    #pragma unroll
    for (int i = 0; i < 8; i++) sum += expf((s[i] - bmax) * 100.f);
    #pragma unroll
    for (int off = 16; off; off >>= 1)
        sum += __shfl_xor_sync(0xffffffffu, sum, off);
    __syncthreads();
    if (lane == 0) wred[warp] = sum;
    __syncthreads();
    if (tid == 0) {
        float tot = 0.f;
        #pragma unroll
        for (int w = 0; w < 8; w++) tot += wred[w];
        out[n] = 0.01f * (logf(tot) - logf(2048.0f)) + bmax;
    }
}

// ---------------- launch ----------------
extern "C" void kernel_launch(void* const* d_in, const int* in_sizes, int n_in,
                              void* d_out, int out_size) {
    const float* X    = (const float*)d_in[0];
    const float* U    = (const float*)d_in[1];
    const float* Y    = (const float*)d_in[2];
    const float* Wt0  = (const float*)d_in[3];
    const float* bt0  = (const float*)d_in[4];
    const float* Wt1  = (const float*)d_in[5];
    const float* bt1  = (const float*)d_in[6];
    const float* Wyu0 = (const float*)d_in[7];
    const float* byu0 = (const float*)d_in[8];
    const float* Wy0  = (const float*)d_in[9];
    const float* Wu0  = (const float*)d_in[10];
    const float* b0   = (const float*)d_in[11];
    const float* Wzu1 = (const float*)d_in[12];
    const float* bzu1 = (const float*)d_in[13];
    const float* Wz1  = (const float*)d_in[14];
    const float* Wyu1 = (const float*)d_in[15];
    const float* byu1 = (const float*)d_in[16];
    const float* Wy1  = (const float*)d_in[17];
    const float* Wu1  = (const float*)d_in[18];
    const float* b1   = (const float*)d_in[19];
    const float* Wzu2 = (const float*)d_in[20];
    const float* bzu2 = (const float*)d_in[21];
    const float* Wz2  = (const float*)d_in[22];
    const float* Wyu2 = (const float*)d_in[23];
    const float* byu2 = (const float*)d_in[24];
    const float* Wy2  = (const float*)d_in[25];
    const float* Wu2  = (const float*)d_in[26];
    const float* b2   = (const float*)d_in[27];

    cudaFuncSetAttribute(main_mma_kernel,
                         cudaFuncAttributeMaxDynamicSharedMemorySize, SMEM_BYTES);

    sp1_kernel<<<256, 256>>>(Wz1);
    stageA_kernel<<<16, 256>>>(X, Wt0, bt0, Wu0, b0);
    stageB_kernel<<<48, 256>>>(Wt1, bt1, Wzu1, bzu1, Wu1, b1);
    stageC_kernel<<<16, 256>>>(Wzu2, bzu2, Wz2);
    smalls_kernel<<<128, 256>>>(X, Wyu0, byu0, Wyu1, byu1,
                                Wyu2, byu2, Wy2, Wu2, b2);
    dim3 grid(32, 128);
    main_mma_kernel<<<grid, 256, SMEM_BYTES>>>(U, Y, Wy0, Wy1);
    lse_kernel<<<128, 256>>>((float*)d_out);
}

// round 17
// speedup vs baseline: 1.2107x; 1.0781x over previous
#include <cuda_runtime.h>
#include <cuda_fp16.h>
#include <math.h>
#include <stdint.h>

// Problem dims
#define N_  128
#define M_  2048
#define DX_ 64
#define DY_ 8
#define DU_ 256
#define DZ_ 256

// ---------------- device scratch (static, no allocations) ----------------
__device__ __align__(16) __half g_sp1h[DZ_ * DZ_];  // fp16(softplus(Wz1)) [k][z]
__device__ __align__(16) float g_WT0  [DX_ * DU_];  // Wt0^T  [d][k]
__device__ __align__(16) float g_WuT0 [DX_ * DZ_];  // Wu0^T
__device__ __align__(16) float g_WT1  [DU_ * DU_];  // Wt1^T
__device__ __align__(16) float g_WzuT1[DU_ * DZ_];  // Wzu1^T
__device__ __align__(16) float g_WuT1 [DU_ * DZ_];  // Wu1^T
__device__ __align__(16) float g_WzuT2[DU_ * DZ_];  // Wzu2^T
__device__ __align__(16) float g_gy0[N_ * DY_];
__device__ __align__(16) float g_c0 [N_ * DZ_];
__device__ __align__(16) float g_gz1[N_ * DZ_];
__device__ __align__(16) float g_gy1[N_ * DY_];
__device__ __align__(16) float g_c1 [N_ * DZ_];
__device__ __align__(16) float g_gk2[N_ * DZ_];     // gz2 * softplus(Wz2)
__device__ __align__(16) float g_w2d[N_ * DY_];     // gy2 * Wy2
__device__ __align__(16) float g_c2 [N_];
__device__ __align__(16) float g_slack[N_ * M_];

__device__ __forceinline__ float softplus_f(float x) {
    return fmaxf(x, 0.f) + log1pf(expf(-fabsf(x)));
}

#define CP_ASYNC16(dst, src) \
    asm volatile("cp.async.cg.shared.global [%0], [%1], 16;" \
        :: "r"((uint32_t)(dst)), "l"(src) : "memory")
#define CP_COMMIT() asm volatile("cp.async.commit_group;" ::: "memory")
#define CP_WAIT0()  asm volatile("cp.async.wait_group 0;" ::: "memory")

__device__ __forceinline__ uint32_t smem_u32(const void* p) {
    uint32_t a;
    asm("{ .reg .u64 t; cvta.to.shared.u64 t, %1; cvt.u32.u64 %0, t; }"
        : "=r"(a) : "l"(p));
    return a;
}

// m16n8k16 fp16 MMA, fp32 accumulate
__device__ __forceinline__ void mma_f16(float* c, const uint32_t* a,
                                        uint32_t b0, uint32_t b1) {
    asm volatile(
        "mma.sync.aligned.m16n8k16.row.col.f32.f16.f16.f32 "
        "{%0,%1,%2,%3}, {%4,%5,%6,%7}, {%8,%9}, {%0,%1,%2,%3};"
        : "+f"(c[0]), "+f"(c[1]), "+f"(c[2]), "+f"(c[3])
        : "r"(a[0]), "r"(a[1]), "r"(a[2]), "r"(a[3]), "r"(b0), "r"(b1));
}

#define LDSM_X4(r0, r1, r2, r3, addr) \
    asm volatile("ldmatrix.sync.aligned.m8n8.x4.shared.b16 {%0,%1,%2,%3}, [%4];" \
        : "=r"(r0), "=r"(r1), "=r"(r2), "=r"(r3) : "r"(addr))

__device__ __forceinline__ uint32_t pack_h2(float lo, float hi) {
    __half2 h = __floats2half2_rn(lo, hi);
    return *(uint32_t*)&h;
}

// ---------------- kernel 0a: fp16(softplus(Wz1)) ----------------
__global__ void sp1_kernel(const float* __restrict__ Wz1) {
    int i = blockIdx.x * 256 + threadIdx.x;
    g_sp1h[i] = __float2half_rn(softplus_f(Wz1[i]));
}

// ---------------- kernel 0b: transpose the 256x256 setup weights ----------------
__global__ void tr256_kernel(const float* __restrict__ Wt1,
                             const float* __restrict__ Wzu1,
                             const float* __restrict__ Wu1,
                             const float* __restrict__ Wzu2)
{
    __shared__ float t[32][33];
    const float* A;
    float* B;
    switch (blockIdx.z) {
        case 0:  A = Wt1;  B = g_WT1;   break;
        case 1:  A = Wzu1; B = g_WzuT1; break;
        case 2:  A = Wu1;  B = g_WuT1;  break;
        default: A = Wzu2; B = g_WzuT2; break;
    }
    const int tx = threadIdx.x, ty = threadIdx.y;
    int xIn = blockIdx.x * 32 + tx;
    int yIn = blockIdx.y * 32 + ty;
    #pragma unroll
    for (int j = 0; j < 32; j += 8)
        t[ty + j][tx] = A[(yIn + j) * 256 + xIn];
    __syncthreads();
    int xOut = blockIdx.y * 32 + tx;
    int yOut = blockIdx.x * 32 + ty;
    #pragma unroll
    for (int j = 0; j < 32; j += 8)
        B[(yOut + j) * 256 + xOut] = t[tx][ty + j];
}

// ---------------- kernel 0c: transpose the 256x64 setup weights ----------------
__global__ void tr64_kernel(const float* __restrict__ Wt0,
                            const float* __restrict__ Wu0)
{
    __shared__ float t[32][33];
    const float* A = blockIdx.z ? Wu0 : Wt0;
    float* B       = blockIdx.z ? g_WuT0 : g_WT0;
    const int tx = threadIdx.x, ty = threadIdx.y;
    int xIn = blockIdx.x * 32 + tx;          // col in A (<64)
    int yIn = blockIdx.y * 32 + ty;          // row in A (<256)
    #pragma unroll
    for (int j = 0; j < 32; j += 8)
        t[ty + j][tx] = A[(yIn + j) * DX_ + xIn];
    __syncthreads();
    int xOut = blockIdx.y * 32 + tx;         // col in B (<256)
    int yOut = blockIdx.x * 32 + ty;         // row in B (<64)
    #pragma unroll
    for (int j = 0; j < 32; j += 8)
        B[(yOut + j) * 256 + xOut] = t[tx][ty + j];
}

// ---------------- kernel 1: per-n setup (coalesced + batched loads) ----------------
// grid 128 (one n per CTA), block 256.
__global__ __launch_bounds__(256) void setup_kernel(
    const float* __restrict__ X,
    const float* __restrict__ bt0,  const float* __restrict__ b0,
    const float* __restrict__ bt1,  const float* __restrict__ bzu1,
    const float* __restrict__ b1,   const float* __restrict__ bzu2,
    const float* __restrict__ Wz2,
    const float* __restrict__ Wyu0, const float* __restrict__ byu0,
    const float* __restrict__ Wyu1, const float* __restrict__ byu1,
    const float* __restrict__ Wyu2, const float* __restrict__ byu2,
    const float* __restrict__ Wy2,
    const float* __restrict__ Wu2,  const float* __restrict__ b2)
{
    __shared__ __align__(16) float xs[DX_];
    __shared__ __align__(16) float u1s[DU_];
    __shared__ __align__(16) float u2s[DU_];
    const int n = blockIdx.x;
    const int k = threadIdx.x;
    const int wid = k >> 5, lane = k & 31;

    if (k < DX_) xs[k] = X[n * DX_ + k];
    __syncthreads();

    // ---- stage 1: u1 = relu(Wt0 x + bt0), c0 = Wu0 x + b0 (coalesced, batched) ----
    {
        float at = 0.f, ac = 0.f;
        #pragma unroll
        for (int d0 = 0; d0 < DX_; d0 += 8) {
            float wt[8], wu[8];
            #pragma unroll
            for (int j = 0; j < 8; ++j) {
                wt[j] = g_WT0 [(d0 + j) * 256 + k];
                wu[j] = g_WuT0[(d0 + j) * 256 + k];
            }
            #pragma unroll
            for (int j = 0; j < 8; ++j) {
                const float x = xs[d0 + j];
                at = fmaf(wt[j], x, at);
                ac = fmaf(wu[j], x, ac);
            }
        }
        u1s[k] = fmaxf(at + bt0[k], 0.f);
        g_c0[n * DZ_ + k] = ac + b0[k];
    }
    // gy0: warp w -> output w (needs only xs)
    {
        float s = 0.f;
        #pragma unroll
        for (int d = lane; d < DX_; d += 32)
            s = fmaf(xs[d], Wyu0[wid * DX_ + d], s);
        #pragma unroll
        for (int off = 16; off; off >>= 1) s += __shfl_xor_sync(0xffffffffu, s, off);
        if (lane == 0) g_gy0[n * DY_ + wid] = s + byu0[wid];
    }
    __syncthreads();

    // ---- stage 2: u2, gz1, c1 (3 transposed weights, 24 loads in flight) ----
    {
        float at = 0.f, az = 0.f, ac = 0.f;
        #pragma unroll 2
        for (int d0 = 0; d0 < DU_; d0 += 8) {
            float w1[8], w2[8], w3[8];
            #pragma unroll
            for (int j = 0; j < 8; ++j) {
                w1[j] = g_WT1  [(d0 + j) * 256 + k];
                w2[j] = g_WzuT1[(d0 + j) * 256 + k];
                w3[j] = g_WuT1 [(d0 + j) * 256 + k];
            }
            #pragma unroll
            for (int j = 0; j < 8; ++j) {
                const float u = u1s[d0 + j];
                at = fmaf(w1[j], u, at);
                az = fmaf(w2[j], u, az);
                ac = fmaf(w3[j], u, ac);
            }
        }
        u2s[k] = fmaxf(at + bt1[k], 0.f);
        g_gz1[n * DZ_ + k] = fmaxf(az + bzu1[k], 0.f);
        g_c1[n * DZ_ + k]  = ac + b1[k];
    }
    // gy1: warp w -> output w (u1s ready after the sync above)
    {
        float s = 0.f;
        #pragma unroll
        for (int d = lane; d < DU_; d += 32)
            s = fmaf(u1s[d], Wyu1[wid * DU_ + d], s);
        #pragma unroll
        for (int off = 16; off; off >>= 1) s += __shfl_xor_sync(0xffffffffu, s, off);
        if (lane == 0) g_gy1[n * DY_ + wid] = s + byu1[wid];
    }
    __syncthreads();

    // ---- stage 3: gk2 ----
    {
        float ag = 0.f;
        #pragma unroll 2
        for (int d0 = 0; d0 < DU_; d0 += 8) {
            float w[8];
            #pragma unroll
            for (int j = 0; j < 8; ++j)
                w[j] = g_WzuT2[(d0 + j) * 256 + k];
            #pragma unroll
            for (int j = 0; j < 8; ++j)
                ag = fmaf(w[j], u2s[d0 + j], ag);
        }
        g_gk2[n * DZ_ + k] = fmaxf(ag + bzu2[k], 0.f) * softplus_f(Wz2[k]);
    }
    // w2d: warp w -> output w; c2: warp 0 second pass
    {
        float s = 0.f;
        #pragma unroll
        for (int d = lane; d < DU_; d += 32)
            s = fmaf(u2s[d], Wyu2[wid * DU_ + d], s);
        #pragma unroll
        for (int off = 16; off; off >>= 1) s += __shfl_xor_sync(0xffffffffu, s, off);
        if (lane == 0) g_w2d[n * DY_ + wid] = (s + byu2[wid]) * Wy2[wid];
    }
    if (wid == 0) {
        float s = 0.f;
        #pragma unroll
        for (int d = lane; d < DU_; d += 32)
            s = fmaf(u2s[d], Wu2[d], s);
        #pragma unroll
        for (int off = 16; off; off >>= 1) s += __shfl_xor_sync(0xffffffffu, s, off);
        if (lane == 0) g_c2[n] = s + b2[0];
    }
}

// ---------------- kernel 2: fp16 HMMA GEMM + full phi + slack (R13, unchanged) ----------------
#define RS    144                   // row stride bytes
#define SM_W     0                  // 2 x 256*144 = 73728
#define SM_A     73728              // 2 x 64*144  = 18432
#define SM_WY0F  92160              // 256 x 12 floats = 12288
#define SM_C0    104448             // 256 floats
#define SM_GZ1   105472
#define SM_C1    106496
#define SM_GK2   107520
#define SM_GY1   108544             // 8 floats (pad 64B)
#define SM_YW    108608
#define SM_PHI   108672             // 256 floats
#define SMEM_BYTES 109696
#define WBUF  36864                 // 256*144
#define ABUF  9216                  // 64*144

extern __shared__ __align__(16) char smem[];

// fill one 64-z A chunk: thread owns row mrow, z quarter s (16 z)
__device__ __forceinline__ void fill_A64(char* Adst, int z0,
                                         const float* wy0f, const float* c0s,
                                         const float* gz1s, const float* ur,
                                         int mrow, int s)
{
    float o[16];
    #pragma unroll
    for (int jj = 0; jj < 16; ++jj) {
        const int j = (jj + s) & 15;           // bank-rotation schedule
        const int z = z0 + s * 16 + j;
        const float4 w0 = *(const float4*)(wy0f + z * 12);
        const float4 w1 = *(const float4*)(wy0f + z * 12 + 4);
        float v = c0s[z];
        v = fmaf(ur[0], w0.x, v); v = fmaf(ur[1], w0.y, v);
        v = fmaf(ur[2], w0.z, v); v = fmaf(ur[3], w0.w, v);
        v = fmaf(ur[4], w1.x, v); v = fmaf(ur[5], w1.y, v);
        v = fmaf(ur[6], w1.z, v); v = fmaf(ur[7], w1.w, v);
        o[j] = fmaxf(v, 0.f) * gz1s[z];
    }
    uint4 p0, p1;
    p0.x = pack_h2(o[0],  o[1]);  p0.y = pack_h2(o[2],  o[3]);
    p0.z = pack_h2(o[4],  o[5]);  p0.w = pack_h2(o[6],  o[7]);
    p1.x = pack_h2(o[8],  o[9]);  p1.y = pack_h2(o[10], o[11]);
    p1.z = pack_h2(o[12], o[13]); p1.w = pack_h2(o[14], o[15]);
    char* dst = Adst + mrow * RS + s * 32;
    *(uint4*)(dst)      = p0;
    *(uint4*)(dst + 16) = p1;
}

__global__ __launch_bounds__(256, 2) void main_mma_kernel(
    const float* __restrict__ U,
    const float* __restrict__ Y,
    const float* __restrict__ Wy0,
    const float* __restrict__ Wy1)
{
    const int tid  = threadIdx.x;
    const int lane = tid & 31;
    const int wid  = tid >> 5;
    const int g    = lane >> 2;     // groupID
    const int t4   = lane & 3;      // thread-in-group
    const int wm   = wid & 1;       // warp m-group (32 rows)
    const int wq   = wid >> 1;      // warp k-col group (64 cols)
    const int n    = blockIdx.y;
    const int m0   = blockIdx.x * 64;

    float* wy0f = (float*)(smem + SM_WY0F);
    float* c0s  = (float*)(smem + SM_C0);
    float* gz1s = (float*)(smem + SM_GZ1);
    float* c1s  = (float*)(smem + SM_C1);
    float* gk2s = (float*)(smem + SM_GK2);
    float* gy1s = (float*)(smem + SM_GY1);
    float* yws  = (float*)(smem + SM_YW);
    float* phiB = (float*)(smem + SM_PHI);
    const uint32_t sb = smem_u32(smem);

    // A-fill assignment
    const int mrow = tid >> 2;      // 0..63
    const int s    = tid & 3;       // z quarter

    // ldmatrix per-lane base addresses (buf 0)
    const int mi = lane >> 3, r = lane & 7;
    uint32_t a_base[2], b_base[4];
    #pragma unroll
    for (int i = 0; i < 2; ++i)
        a_base[i] = sb + SM_A + (uint32_t)((wm * 32 + i * 16 + (mi & 1) * 8 + r) * RS
                                           + (mi >> 1) * 16);
    #pragma unroll
    for (int jp = 0; jp < 4; ++jp)
        b_base[jp] = sb + SM_W + (uint32_t)((wq * 64 + jp * 16 + (mi >> 1) * 8 + r) * RS
                                            + (mi & 1) * 16);

    // ---- kick off W chunk 0 cp.async ----
    {
        const uint32_t Wdst = sb + SM_W;
        #pragma unroll
        for (int it = 0; it < 8; ++it) {
            int idx = it * 256 + tid;
            int q = idx >> 3, seg = idx & 7;
            CP_ASYNC16(Wdst + (uint32_t)(q * RS + seg * 16),
                       &g_sp1h[q * 256 + seg * 8]);
        }
        CP_COMMIT();
    }

    // ---- prologue: per-n consts ----
    c0s[tid]  = g_c0 [n * DZ_ + tid];
    gz1s[tid] = g_gz1[n * DZ_ + tid];
    c1s[tid]  = g_c1 [n * DZ_ + tid];
    gk2s[tid] = g_gk2[n * DZ_ + tid];
    if (tid < DY_) {
        gy1s[tid] = g_gy1[n * DY_ + tid];
        yws[tid]  = Y[n * DY_ + tid] - g_w2d[n * DY_ + tid];
    }
    {   // wy0f[z][d] = Wy0[z][d] * gy0[n][d], stride 12 floats
        const int z = tid;
        float4 wa = *(const float4*)&Wy0[z * 8];
        float4 wb = *(const float4*)&Wy0[z * 8 + 4];
        float4 ga = *(const float4*)&g_gy0[n * DY_];
        float4 gb = *(const float4*)&g_gy0[n * DY_ + 4];
        *(float4*)(wy0f + z * 12)     = make_float4(wa.x*ga.x, wa.y*ga.y, wa.z*ga.z, wa.w*ga.w);
        *(float4*)(wy0f + z * 12 + 4) = make_float4(wb.x*gb.x, wb.y*gb.y, wb.z*gb.z, wb.w*gb.w);
    }
    float ur[8];
    {
        float4 u0 = *(const float4*)&U[(m0 + mrow) * 8];
        float4 u1 = *(const float4*)&U[(m0 + mrow) * 8 + 4];
        ur[0]=u0.x; ur[1]=u0.y; ur[2]=u0.z; ur[3]=u0.w;
        ur[4]=u1.x; ur[5]=u1.y; ur[6]=u1.z; ur[7]=u1.w;
    }
    __syncthreads();

    fill_A64(smem + SM_A, 0, wy0f, c0s, gz1s, ur, mrow, s);
    CP_WAIT0();
    __syncthreads();

    float acc[2][8][4];
    #pragma unroll
    for (int i = 0; i < 2; ++i)
        #pragma unroll
        for (int j = 0; j < 8; ++j)
            #pragma unroll
            for (int q = 0; q < 4; ++q) acc[i][j][q] = 0.f;

    // ---- main loop: 4 real 64-z chunks + 1 pseudo k16 chunk ----
    #pragma unroll
    for (int c = 0; c < 5; ++c) {
        const int buf = c & 1, nb = buf ^ 1;

        if (c < 4) {
            if (c + 1 < 4) {
                const int z0n = (c + 1) * 64;
                const uint32_t Wdst = sb + SM_W + nb * WBUF;
                #pragma unroll
                for (int it = 0; it < 8; ++it) {
                    int idx = it * 256 + tid;
                    int q = idx >> 3, seg = idx & 7;
                    CP_ASYNC16(Wdst + (uint32_t)(q * RS + seg * 16),
                               &g_sp1h[q * 256 + z0n + seg * 8]);
                }
                CP_COMMIT();
                fill_A64(smem + SM_A + nb * ABUF, z0n, wy0f, c0s, gz1s, ur, mrow, s);
            } else {
                // pseudo chunk (k16): A[m][0..7]=U, 8..15=0; W[q][0..7]=Wy1*gy1
                char* Adst = smem + SM_A + nb * ABUF;
                if (s == 0) {
                    uint4 av, zv;
                    av.x = pack_h2(ur[0], ur[1]); av.y = pack_h2(ur[2], ur[3]);
                    av.z = pack_h2(ur[4], ur[5]); av.w = pack_h2(ur[6], ur[7]);
                    zv = make_uint4(0, 0, 0, 0);
                    *(uint4*)(Adst + mrow * RS)      = av;
                    *(uint4*)(Adst + mrow * RS + 16) = zv;
                }
                char* Wdst = smem + SM_W + nb * WBUF;
                const int q = tid;
                float4 w0 = *(const float4*)&Wy1[q * 8];
                float4 w1 = *(const float4*)&Wy1[q * 8 + 4];
                uint4 wv;
                wv.x = pack_h2(w0.x * gy1s[0], w0.y * gy1s[1]);
                wv.y = pack_h2(w0.z * gy1s[2], w0.w * gy1s[3]);
                wv.z = pack_h2(w1.x * gy1s[4], w1.y * gy1s[5]);
                wv.w = pack_h2(w1.z * gy1s[6], w1.w * gy1s[7]);
                *(uint4*)(Wdst + q * RS)      = wv;
                *(uint4*)(Wdst + q * RS + 16) = make_uint4(0, 0, 0, 0);
            }
        }

        // MMA on current buffer
        {
            const uint32_t aoff = buf * ABUF;
            const uint32_t woff = buf * WBUF;
            const int nks = (c == 4) ? 1 : 4;
            #pragma unroll
            for (int ks = 0; ks < 4; ++ks) {
                if (ks >= nks) break;
                const uint32_t kb = ks * 32;
                uint32_t a0[4], a1[4];
                LDSM_X4(a0[0], a0[1], a0[2], a0[3], a_base[0] + aoff + kb);
                LDSM_X4(a1[0], a1[1], a1[2], a1[3], a_base[1] + aoff + kb);
                #pragma unroll
                for (int jp = 0; jp < 4; ++jp) {
                    uint32_t b[4];
                    LDSM_X4(b[0], b[1], b[2], b[3], b_base[jp] + woff + kb);
                    mma_f16(acc[0][jp * 2],     a0, b[0], b[1]);
                    mma_f16(acc[1][jp * 2],     a1, b[0], b[1]);
                    mma_f16(acc[0][jp * 2 + 1], a0, b[2], b[3]);
                    mma_f16(acc[1][jp * 2 + 1], a1, b[2], b[3]);
                }
            }
        }
        if (c < 3) CP_WAIT0();
        __syncthreads();
    }

    // ---- epilogue: phi over this CTA's full 256 k ----
    float p[4] = {0.f, 0.f, 0.f, 0.f};
    #pragma unroll
    for (int j = 0; j < 8; ++j) {
        const int q = wq * 64 + j * 8 + 2 * t4;
        const float ca = c1s[q],  cb = c1s[q + 1];
        const float ga = gk2s[q], gb = gk2s[q + 1];
        #pragma unroll
        for (int i = 0; i < 2; ++i) {
            p[i*2+0] = fmaf(fmaxf(acc[i][j][0] + ca, 0.f), ga, p[i*2+0]);
            p[i*2+0] = fmaf(fmaxf(acc[i][j][1] + cb, 0.f), gb, p[i*2+0]);
            p[i*2+1] = fmaf(fmaxf(acc[i][j][2] + ca, 0.f), ga, p[i*2+1]);
            p[i*2+1] = fmaf(fmaxf(acc[i][j][3] + cb, 0.f), gb, p[i*2+1]);
        }
    }
    #pragma unroll
    for (int idx = 0; idx < 4; ++idx) {
        float v = p[idx];
        v += __shfl_xor_sync(0xffffffffu, v, 1);
        v += __shfl_xor_sync(0xffffffffu, v, 2);
        if (t4 == 0) {
            const int i = idx >> 1, h = idx & 1;
            phiB[wq * 64 + wm * 32 + i * 16 + h * 8 + g] = v;
        }
    }
    __syncthreads();
    if (tid < 64) {
        float phi = phiB[tid] + phiB[64 + tid] + phiB[128 + tid] + phiB[192 + tid];
        float4 u0 = *(const float4*)&U[(m0 + tid) * 8];
        float4 u1 = *(const float4*)&U[(m0 + tid) * 8 + 4];
        float sl = -g_c2[n] - phi;
        sl = fmaf(u0.x, yws[0], sl); sl = fmaf(u0.y, yws[1], sl);
        sl = fmaf(u0.z, yws[2], sl); sl = fmaf(u0.w, yws[3], sl);
        sl = fmaf(u1.x, yws[4], sl); sl = fmaf(u1.y, yws[5], sl);
        sl = fmaf(u1.z, yws[6], sl); sl = fmaf(u1.w, yws[7], sl);
        g_slack[n * M_ + m0 + tid] = sl;
    }
}

// ---------------- kernel 3: row-wise stable logsumexp ----------------
__global__ void lse_kernel(float* __restrict__ out) {
    __shared__ float wred[8];
    __shared__ float bmax_s;
    const int n = blockIdx.x, tid = threadIdx.x;
    const int lane = tid & 31, warp = tid >> 5;

    float s[8];
    #pragma unroll
    for (int i = 0; i < 8; i++) s[i] = g_slack[n * M_ + tid + i * 256];

    float mx = s[0];
    #pragma unroll
    for (int i = 1; i < 8; i++) mx = fmaxf(mx, s[i]);
    #pragma unroll
    for (int off = 16; off; off >>= 1)
        mx = fmaxf(mx, __shfl_xor_sync(0xffffffffu, mx, off));
    if (lane == 0) wred[warp] = mx;
    __syncthreads();
    if (tid == 0) {
        float m2 = wred[0];
        #pragma unroll
        for (int w = 1; w < 8; w++) m2 = fmaxf(m2, wred[w]);
        bmax_s = m2;
    }
    __syncthreads();
    const float bmax = bmax_s;

    float sum = 0.f;
    #pragma unroll
    for (int i = 0; i < 8; i++) sum += expf((s[i] - bmax) * 100.f);
    #pragma unroll
    for (int off = 16; off; off >>= 1)
        sum += __shfl_xor_sync(0xffffffffu, sum, off);
    __syncthreads();
    if (lane == 0) wred[warp] = sum;
    __syncthreads();
    if (tid == 0) {
        float tot = 0.f;
        #pragma unroll
        for (int w = 0; w < 8; w++) tot += wred[w];
        out[n] = 0.01f * (logf(tot) - logf(2048.0f)) + bmax;
    }
}

// ---------------- launch ----------------
extern "C" void kernel_launch(void* const* d_in, const int* in_sizes, int n_in,
                              void* d_out, int out_size) {
    const float* X    = (const float*)d_in[0];
    const float* U    = (const float*)d_in[1];
    const float* Y    = (const float*)d_in[2];
    const float* Wt0  = (const float*)d_in[3];
    const float* bt0  = (const float*)d_in[4];
    const float* Wt1  = (const float*)d_in[5];
    const float* bt1  = (const float*)d_in[6];
    const float* Wyu0 = (const float*)d_in[7];
    const float* byu0 = (const float*)d_in[8];
    const float* Wy0  = (const float*)d_in[9];
    const float* Wu0  = (const float*)d_in[10];
    const float* b0   = (const float*)d_in[11];
    const float* Wzu1 = (const float*)d_in[12];
    const float* bzu1 = (const float*)d_in[13];
    const float* Wz1  = (const float*)d_in[14];
    const float* Wyu1 = (const float*)d_in[15];
    const float* byu1 = (const float*)d_in[16];
    const float* Wy1  = (const float*)d_in[17];
    const float* Wu1  = (const float*)d_in[18];
    const float* b1   = (const float*)d_in[19];
    const float* Wzu2 = (const float*)d_in[20];
    const float* bzu2 = (const float*)d_in[21];
    const float* Wz2  = (const float*)d_in[22];
    const float* Wyu2 = (const float*)d_in[23];
    const float* byu2 = (const float*)d_in[24];
    const float* Wy2  = (const float*)d_in[25];
    const float* Wu2  = (const float*)d_in[26];
    const float* b2   = (const float*)d_in[27];

    cudaFuncSetAttribute(main_mma_kernel,
                         cudaFuncAttributeMaxDynamicSharedMemorySize, SMEM_BYTES);

    sp1_kernel<<<256, 256>>>(Wz1);
    {
        dim3 blk(32, 8);
        tr256_kernel<<<dim3(8, 8, 4), blk>>>(Wt1, Wzu1, Wu1, Wzu2);
        tr64_kernel<<<dim3(2, 8, 2), blk>>>(Wt0, Wu0);
    }
    setup_kernel<<<128, 256>>>(X, bt0, b0, bt1, bzu1, b1, bzu2, Wz2,
                               Wyu0, byu0, Wyu1, byu1, Wyu2, byu2,
                               Wy2, Wu2, b2);
    dim3 grid(32, 128);
    main_mma_kernel<<<grid, 256, SMEM_BYTES>>>(U, Y, Wy0, Wy1);
    lse_kernel<<<128, 256>>>((float*)d_out);
}